// round 12
// baseline (speedup 1.0000x reference)
#include <cuda_runtime.h>
#include <cstdint>

#define NN 16384
#define HH 64

// ---------------- scratch (no allocs allowed) ----------------
__device__ float g_t [NN*HH];   // h @ W_rel^T   (tf32-pre-rounded, B operand)
__device__ float g_r [NN*HH];   // h @ W_root^T  (epilogue add, full fp32)
__device__ float g_hA[NN*HH];   // layer outputs ping
__device__ float g_hB[NN*HH];   // layer outputs pong

// ---------------- helpers ----------------
__device__ __forceinline__ unsigned f2tf32(float x) {
    unsigned u;
    asm("cvt.rna.tf32.f32 %0, %1;" : "=r"(u) : "f"(x));
    return u;
}
__device__ __forceinline__ void cp16(void* s, const void* g) {
    unsigned sa = (unsigned)__cvta_generic_to_shared(s);
    asm volatile("cp.async.cg.shared.global [%0], [%1], 16;\n" :: "r"(sa), "l"(g));
}

// =============================================================
// small_gemm: [t | r] = h[N,K] @ [W_rel | W_root]^T  (both [64,K])
// CTA: 128 rows x 128 cols, 256 threads, 8x8 outputs/thread.
// t is stored ALREADY tf32-rounded (big_gemm skips the B cvt).
// =============================================================
__global__ __launch_bounds__(256, 1) void small_gemm(
    const float* __restrict__ h, const float* __restrict__ Wrel,
    const float* __restrict__ Wroot, float* __restrict__ t,
    float* __restrict__ r, int K)
{
    extern __shared__ float sm[];
    const int Kp = K + 4;             // 260 or 68
    float* Ws = sm;                   // [128][Kp]
    float* hs = sm + 128 * Kp;        // [128][68]

    const int tid = threadIdx.x;
    const int i0  = blockIdx.x * 128;

    const int kq = K / 4;
    for (int idx = tid; idx < 128 * kq; idx += 256) {
        int row = idx / kq;
        int kv  = (idx % kq) * 4;
        const float* src = (row < 64) ? (Wrel + (size_t)row * K + kv)
                                      : (Wroot + (size_t)(row - 64) * K + kv);
        *(float4*)&Ws[row * Kp + kv] = *(const float4*)src;
    }

    const int r8 = tid >> 4;
    const int c8 = tid & 15;
    float acc[8][8];
    #pragma unroll
    for (int a = 0; a < 8; ++a)
        #pragma unroll
        for (int b = 0; b < 8; ++b) acc[a][b] = 0.f;

    for (int k0 = 0; k0 < K; k0 += 64) {
        __syncthreads();
        for (int idx = tid; idx < 128 * 16; idx += 256) {
            int row = idx >> 4;
            int kv  = (idx & 15) * 4;
            *(float4*)&hs[row * 68 + kv] =
                *(const float4*)&h[(size_t)(i0 + row) * K + k0 + kv];
        }
        __syncthreads();
        #pragma unroll 4
        for (int k4 = 0; k4 < 64; k4 += 4) {
            float4 hv[8];
            #pragma unroll
            for (int ii = 0; ii < 8; ++ii)
                hv[ii] = *(const float4*)&hs[(r8 + 16 * ii) * 68 + k4];
            #pragma unroll
            for (int jj = 0; jj < 8; ++jj) {
                float4 wv = *(const float4*)&Ws[(c8 + 16 * jj) * Kp + k0 + k4];
                #pragma unroll
                for (int ii = 0; ii < 8; ++ii) {
                    acc[ii][jj] += hv[ii].x * wv.x + hv[ii].y * wv.y
                                 + hv[ii].z * wv.z + hv[ii].w * wv.w;
                }
            }
        }
    }

    #pragma unroll
    for (int jj = 0; jj < 8; ++jj) {
        int col = c8 + 16 * jj;
        #pragma unroll
        for (int ii = 0; ii < 8; ++ii) {
            int i = i0 + r8 + 16 * ii;
            if (col < 64)
                t[(size_t)i * 64 + col] = __uint_as_float(f2tf32(acc[ii][jj]));
            else
                r[(size_t)i * 64 + (col - 64)] = acc[ii][jj];
        }
    }
}

// =============================================================
// big_gemm: out[i,f] = relu( sum_j adj[j,i]*t[j,f] + bias[f] + Radd[i,f] )
// CTA tile 128x64, KT=32, 8-stage cp.async, tf32 mma.sync, 512 threads.
// 16 warps: kh(2) x wm(4) x wn(2). Warp pairs split the 4 k-substeps
// (2 each); halves merged via SMEM before the fused epilogue.
// Strides 136/72 (== 8 mod 32) -> conflict-free fragment LDS.
// =============================================================
#define STAGES  8
#define ASTRIDE 136
#define BSTRIDE 72
#define ASZ (32 * ASTRIDE)
#define BSZ (32 * BSTRIDE)
#define REDSTRIDE 72

__global__ __launch_bounds__(512, 1) void big_gemm(
    const float* __restrict__ adj, const float* __restrict__ Bmat,
    const float* __restrict__ Radd, const float* __restrict__ bias,
    float* __restrict__ out)
{
    extern __shared__ float sm[];
    float* As  = sm;                    // [STAGES][32][136]
    float* Bs  = sm + STAGES * ASZ;     // [STAGES][32][72]
    float* red = sm;                    // reduction buffer (reused post-loop)

    const int tid  = threadIdx.x;
    const int lane = tid & 31;
    const int warp = tid >> 5;
    const int kh   = warp >> 3;         // 0..1 : k-substep half
    const int wm   = (warp >> 1) & 3;   // 0..3 : rows wm*32
    const int wn   = warp & 1;          // 0..1 : cols wn*32
    const int m0   = blockIdx.x * 128;

    float acc[2][4][4];
    #pragma unroll
    for (int a = 0; a < 2; ++a)
        #pragma unroll
        for (int b = 0; b < 4; ++b)
            #pragma unroll
            for (int c = 0; c < 4; ++c) acc[a][b][c] = 0.f;

    auto load_stage = [&](int s, int kc) {
        const float* ga = adj + (size_t)kc * 32 * NN + m0;
        float* as = As + s * ASZ;
        #pragma unroll
        for (int it = 0; it < 2; ++it) {       // 32x128 floats = 1024 float4
            int idx = it * 512 + tid;
            int k = idx >> 5, mv = (idx & 31) * 4;
            cp16(&as[k * ASTRIDE + mv], ga + (size_t)k * NN + mv);
        }
        const float* gb = Bmat + (size_t)kc * 32 * 64;
        float* bs = Bs + s * BSZ;
        {
            int k = tid >> 4, nv = (tid & 15) * 4;  // 512 float4
            cp16(&bs[k * BSTRIDE + nv], gb + k * 64 + nv);
        }
        asm volatile("cp.async.commit_group;\n");
    };

    #pragma unroll
    for (int s = 0; s < STAGES - 1; ++s) load_stage(s, s);

    const int NK = NN / 32;            // 512 chunks
    for (int kc = 0; kc < NK; ++kc) {
        asm volatile("cp.async.wait_group %0;\n" :: "n"(STAGES - 2));
        __syncthreads();
        if (kc + STAGES - 1 < NK)
            load_stage((kc + STAGES - 1) & (STAGES - 1), kc + STAGES - 1);

        const float* as = As + (kc & (STAGES - 1)) * ASZ;
        const float* bs = Bs + (kc & (STAGES - 1)) * BSZ;

        #pragma unroll
        for (int ks = 0; ks < 2; ++ks) {
            const int kk = (kh * 2 + ks) * 8 + (lane & 3);
            const int rb = wm * 32 + (lane >> 2);
            unsigned Af[2][4];
            #pragma unroll
            for (int mf = 0; mf < 2; ++mf) {
                Af[mf][0] = f2tf32(as[kk * ASTRIDE + rb + mf * 16]);
                Af[mf][1] = f2tf32(as[kk * ASTRIDE + rb + mf * 16 + 8]);
                Af[mf][2] = f2tf32(as[(kk + 4) * ASTRIDE + rb + mf * 16]);
                Af[mf][3] = f2tf32(as[(kk + 4) * ASTRIDE + rb + mf * 16 + 8]);
            }
            const int cb = wn * 32 + (lane >> 2);
            unsigned Bf[4][2];
            #pragma unroll
            for (int nf = 0; nf < 4; ++nf) {   // t pre-rounded: raw bits OK
                Bf[nf][0] = __float_as_uint(bs[kk * BSTRIDE + cb + nf * 8]);
                Bf[nf][1] = __float_as_uint(bs[(kk + 4) * BSTRIDE + cb + nf * 8]);
            }
            #pragma unroll
            for (int mf = 0; mf < 2; ++mf)
                #pragma unroll
                for (int nf = 0; nf < 4; ++nf)
                    asm volatile(
                        "mma.sync.aligned.m16n8k8.row.col.f32.tf32.tf32.f32 "
                        "{%0,%1,%2,%3}, {%4,%5,%6,%7}, {%8,%9}, {%0,%1,%2,%3};\n"
                        : "+f"(acc[mf][nf][0]), "+f"(acc[mf][nf][1]),
                          "+f"(acc[mf][nf][2]), "+f"(acc[mf][nf][3])
                        : "r"(Af[mf][0]), "r"(Af[mf][1]),
                          "r"(Af[mf][2]), "r"(Af[mf][3]),
                          "r"(Bf[nf][0]), "r"(Bf[nf][1]));
        }
    }

    // drain async copies before reusing SMEM as the reduction buffer
    asm volatile("cp.async.wait_group 0;\n");
    __syncthreads();

    // kh=1 warps publish their half-K partials
    if (kh == 1) {
        #pragma unroll
        for (int mf = 0; mf < 2; ++mf) {
            int rl = wm * 32 + mf * 16 + (lane >> 2);
            #pragma unroll
            for (int nf = 0; nf < 4; ++nf) {
                int col = wn * 32 + nf * 8 + (lane & 3) * 2;
                *(float2*)&red[rl * REDSTRIDE + col] =
                    make_float2(acc[mf][nf][0], acc[mf][nf][1]);
                *(float2*)&red[(rl + 8) * REDSTRIDE + col] =
                    make_float2(acc[mf][nf][2], acc[mf][nf][3]);
            }
        }
    }
    __syncthreads();

    // kh=0 warps merge + fused epilogue (bias + root term + relu)
    if (kh == 0) {
        #pragma unroll
        for (int mf = 0; mf < 2; ++mf) {
            int rl = wm * 32 + mf * 16 + (lane >> 2);
            int i0 = m0 + rl;
            #pragma unroll
            for (int nf = 0; nf < 4; ++nf) {
                int col = wn * 32 + nf * 8 + (lane & 3) * 2;
                float bv0 = bias[col], bv1 = bias[col + 1];
                {
                    float2 p  = *(const float2*)&red[rl * REDSTRIDE + col];
                    float2 rv = *(const float2*)&Radd[(size_t)i0 * 64 + col];
                    float2 o;
                    o.x = fmaxf(acc[mf][nf][0] + p.x + bv0 + rv.x, 0.f);
                    o.y = fmaxf(acc[mf][nf][1] + p.y + bv1 + rv.y, 0.f);
                    *(float2*)&out[(size_t)i0 * 64 + col] = o;
                }
                {
                    float2 p  = *(const float2*)&red[(rl + 8) * REDSTRIDE + col];
                    float2 rv = *(const float2*)&Radd[(size_t)(i0 + 8) * 64 + col];
                    float2 o;
                    o.x = fmaxf(acc[mf][nf][2] + p.x + bv0 + rv.x, 0.f);
                    o.y = fmaxf(acc[mf][nf][3] + p.y + bv1 + rv.y, 0.f);
                    *(float2*)&out[(size_t)(i0 + 8) * 64 + col] = o;
                }
            }
        }
    }
}

// =============================================================
// kernel_launch: 6 kernels, default stream, graph-capturable.
// =============================================================
extern "C" void kernel_launch(void* const* d_in, const int* in_sizes, int n_in,
                              void* d_out, int out_size) {
    (void)in_sizes; (void)n_in; (void)out_size;
    const float* X   = (const float*)d_in[0];
    const float* adj = (const float*)d_in[1];
    const float* Wr0 = (const float*)d_in[2];
    const float* b0  = (const float*)d_in[3];
    const float* Wo0 = (const float*)d_in[4];
    const float* Wr1 = (const float*)d_in[5];
    const float* b1  = (const float*)d_in[6];
    const float* Wo1 = (const float*)d_in[7];
    const float* Wr2 = (const float*)d_in[8];
    const float* b2  = (const float*)d_in[9];
    const float* Wo2 = (const float*)d_in[10];
    float* out = (float*)d_out;

    float *t, *r, *hA, *hB;
    cudaGetSymbolAddress((void**)&t,  g_t);
    cudaGetSymbolAddress((void**)&r,  g_r);
    cudaGetSymbolAddress((void**)&hA, g_hA);
    cudaGetSymbolAddress((void**)&hB, g_hB);

    const int SMEM_SMALL0 = (128 * 260 + 128 * 68) * 4;  // 167936 (K=256)
    const int SMEM_SMALL1 = (128 * 68 + 128 * 68) * 4;   // 69632  (K=64)
    const int SMEM_BIG    = STAGES * (ASZ + BSZ) * 4;    // 212992

    cudaFuncSetAttribute(small_gemm, cudaFuncAttributeMaxDynamicSharedMemorySize, SMEM_SMALL0);
    cudaFuncSetAttribute(big_gemm,   cudaFuncAttributeMaxDynamicSharedMemorySize, SMEM_BIG);

    // layer 0 (F_in = 256)
    small_gemm<<<128, 256, SMEM_SMALL0>>>(X,  Wr0, Wo0, t, r, 256);
    big_gemm  <<<128, 512, SMEM_BIG   >>>(adj, t, r, b0, hA);
    // layer 1 (F_in = 64)
    small_gemm<<<128, 256, SMEM_SMALL1>>>(hA, Wr1, Wo1, t, r, 64);
    big_gemm  <<<128, 512, SMEM_BIG   >>>(adj, t, r, b1, hB);
    // layer 2 (F_in = 64)
    small_gemm<<<128, 256, SMEM_SMALL1>>>(hB, Wr2, Wo2, t, r, 64);
    big_gemm  <<<128, 512, SMEM_BIG   >>>(adj, t, r, b2, out);
}

// round 16
// speedup vs baseline: 1.0562x; 1.0562x over previous
#include <cuda_runtime.h>
#include <cstdint>

#define NN 16384
#define KT 64
#define NKC (NN / KT)          // 256 k-chunks
#define AS  136                // A smem stride (== 8 mod 32, conflict-free frags)
#define BSx 72                 // B smem stride (== 8 mod 32, conflict-free LDS.64)
#define ASTG (KT * AS)         // 8704 floats
#define BSTG (KT * BSx)        // 4608 floats
#define STG  (ASTG + BSTG)     // 13312 floats per stage
#define SMEM_BIG (3 * STG * 4) // 159744 bytes

// ---------------- scratch (no allocs allowed) ----------------
__device__ float g_t [64 * NN];   // tT[f][j], j-contig, tf32-pre-rounded, k-pair-permuted
__device__ float g_r [NN * 64];   // h @ W_root^T (epilogue add)
__device__ float g_hA[NN * 64];
__device__ float g_hB[NN * 64];

// ---------------- helpers ----------------
__device__ __forceinline__ unsigned f2tf32(float x) {
    unsigned u;
    asm("cvt.rna.tf32.f32 %0, %1;" : "=r"(u) : "f"(x));
    return u;
}
__device__ __forceinline__ void cp16(void* s, const void* g) {
    unsigned sa = (unsigned)__cvta_generic_to_shared(s);
    asm volatile("cp.async.cg.shared.global [%0], [%1], 16;\n" :: "r"(sa), "l"(g));
}

// =============================================================
// small_gemm: tT[f][perm(j)] = tf32(h @ W_rel^T)^T ;  r = h @ W_root^T
// perm: within each 8-block of j, j -> (j&3)*2 + ((j>>2)&1), so that
// big_gemm's (k, k+4) B-fragment pair is a contiguous float2.
// CTA 128 rows x 128 cols, 256 threads, 8x8 per thread.
// =============================================================
__global__ __launch_bounds__(256, 1) void small_gemm(
    const float* __restrict__ h, const float* __restrict__ Wrel,
    const float* __restrict__ Wroot, float* __restrict__ tT,
    float* __restrict__ r, int K)
{
    extern __shared__ float sm[];
    const int Kp = K + 4;
    float* Ws = sm;                   // [128][Kp]
    float* hs = sm + 128 * Kp;        // [128][68]

    const int tid = threadIdx.x;
    const int i0  = blockIdx.x * 128;

    const int kq = K / 4;
    for (int idx = tid; idx < 128 * kq; idx += 256) {
        int row = idx / kq;
        int kv  = (idx % kq) * 4;
        const float* src = (row < 64) ? (Wrel + (size_t)row * K + kv)
                                      : (Wroot + (size_t)(row - 64) * K + kv);
        *(float4*)&Ws[row * Kp + kv] = *(const float4*)src;
    }

    const int r8 = tid >> 4;
    const int c8 = tid & 15;
    float acc[8][8];
    #pragma unroll
    for (int a = 0; a < 8; ++a)
        #pragma unroll
        for (int b = 0; b < 8; ++b) acc[a][b] = 0.f;

    for (int k0 = 0; k0 < K; k0 += 64) {
        __syncthreads();
        for (int idx = tid; idx < 128 * 16; idx += 256) {
            int row = idx >> 4;
            int kv  = (idx & 15) * 4;
            *(float4*)&hs[row * 68 + kv] =
                *(const float4*)&h[(size_t)(i0 + row) * K + k0 + kv];
        }
        __syncthreads();
        #pragma unroll 4
        for (int k4 = 0; k4 < 64; k4 += 4) {
            float4 hv[8];
            #pragma unroll
            for (int ii = 0; ii < 8; ++ii)
                hv[ii] = *(const float4*)&hs[(r8 + 16 * ii) * 68 + k4];
            #pragma unroll
            for (int jj = 0; jj < 8; ++jj) {
                float4 wv = *(const float4*)&Ws[(c8 + 16 * jj) * Kp + k0 + k4];
                #pragma unroll
                for (int ii = 0; ii < 8; ++ii) {
                    acc[ii][jj] += hv[ii].x * wv.x + hv[ii].y * wv.y
                                 + hv[ii].z * wv.z + hv[ii].w * wv.w;
                }
            }
        }
    }

    // stage t transposed + k-pair-permuted in SMEM; r straight to gmem
    __syncthreads();
    float* stage = sm;                // [64][132]
    #pragma unroll
    for (int jj = 0; jj < 8; ++jj) {
        int col = c8 + 16 * jj;
        #pragma unroll
        for (int ii = 0; ii < 8; ++ii) {
            int il  = r8 + 16 * ii;
            float v = acc[ii][jj];
            if (col < 64) {
                int pil = (il & ~7) | ((il & 3) << 1) | ((il >> 2) & 1);
                stage[col * 132 + pil] = __uint_as_float(f2tf32(v));
            } else {
                r[(size_t)(i0 + il) * 64 + (col - 64)] = v;
            }
        }
    }
    __syncthreads();
    #pragma unroll
    for (int it = 0; it < 8; ++it) {
        int idx = it * 256 + tid;
        int f = idx >> 5, q = idx & 31;
        *(float4*)&tT[(size_t)f * NN + i0 + q * 4] =
            *(const float4*)&stage[f * 132 + q * 4];
    }
}

// =============================================================
// big_gemm: out[i,f] = relu( sum_j adj[j,i]*t[j,f] + bias[f] + Radd[i,f] )
// grid 128 (one wave), 1024 threads (32 warps), CTA tile 128x64.
// KT=64, 3-stage cp.async (dist 2), tf32 mma.sync.
// Warps: kh(4) x wm(4) x wn(2); warp tile 32x32; each warp does 2 of the
// 8 k-substeps. 4-way partials merged via SMEM, fused epilogue.
// =============================================================
__global__ __launch_bounds__(1024) void big_gemm(
    const float* __restrict__ adj, const float* __restrict__ Bg,
    const float* __restrict__ Radd, const float* __restrict__ bias,
    float* __restrict__ out)
{
    extern __shared__ float sm[];
    const int tid  = threadIdx.x;
    const int lane = tid & 31;
    const int warp = tid >> 5;
    const int kh   = warp >> 3;         // 0..3 : k-substep group
    const int wm   = (warp >> 1) & 3;   // 0..3 : rows wm*32
    const int wn   = warp & 1;          // 0..1 : cols wn*32
    const int m0   = blockIdx.x * 128;

    float acc[2][4][4];
    #pragma unroll
    for (int a = 0; a < 2; ++a)
        #pragma unroll
        for (int b = 0; b < 4; ++b)
            #pragma unroll
            for (int c = 0; c < 4; ++c) acc[a][b][c] = 0.f;

    auto issue = [&](int kc) {
        float* a = sm + (kc % 3) * STG;
        const float* ga = adj + (size_t)kc * KT * NN + m0;
        #pragma unroll
        for (int it = 0; it < 2; ++it) {          // 64k x 128m floats
            int item = it * 1024 + tid;
            int k = item >> 5, mq = (item & 31) * 4;
            cp16(&a[k * AS + mq], ga + (size_t)k * NN + mq);
        }
        float* b = a + ASTG;                      // 64n x 64k floats
        int n = tid >> 4, q = (tid & 15) * 4;
        cp16(&b[n * BSx + q], Bg + (size_t)n * NN + kc * KT + q);
    };

    issue(0); asm volatile("cp.async.commit_group;\n");
    issue(1); asm volatile("cp.async.commit_group;\n");

    for (int kc = 0; kc < NKC; ++kc) {
        asm volatile("cp.async.wait_group 1;\n");
        __syncthreads();
        if (kc + 2 < NKC) issue(kc + 2);
        asm volatile("cp.async.commit_group;\n");

        const float* as = sm + (kc % 3) * STG;
        const float* bs = as + ASTG;

        #pragma unroll
        for (int s2 = 0; s2 < 2; ++s2) {
            const int s  = kh * 2 + s2;           // 0..7
            const int kA = s * 8 + (lane & 3);
            const int rb = wm * 32 + (lane >> 2);
            unsigned Af[2][4];
            #pragma unroll
            for (int mf = 0; mf < 2; ++mf) {
                Af[mf][0] = f2tf32(as[kA * AS + rb + mf * 16]);
                Af[mf][1] = f2tf32(as[kA * AS + rb + mf * 16 + 8]);
                Af[mf][2] = f2tf32(as[(kA + 4) * AS + rb + mf * 16]);
                Af[mf][3] = f2tf32(as[(kA + 4) * AS + rb + mf * 16 + 8]);
            }
            const int cb = wn * 32 + (lane >> 2);
            unsigned Bf[4][2];
            #pragma unroll
            for (int nf = 0; nf < 4; ++nf) {      // permuted pair -> one LDS.64
                float2 v = *(const float2*)&bs[(cb + nf * 8) * BSx
                                               + s * 8 + 2 * (lane & 3)];
                Bf[nf][0] = __float_as_uint(v.x);
                Bf[nf][1] = __float_as_uint(v.y);
            }
            #pragma unroll
            for (int mf = 0; mf < 2; ++mf)
                #pragma unroll
                for (int nf = 0; nf < 4; ++nf)
                    asm volatile(
                        "mma.sync.aligned.m16n8k8.row.col.f32.tf32.tf32.f32 "
                        "{%0,%1,%2,%3}, {%4,%5,%6,%7}, {%8,%9}, {%0,%1,%2,%3};\n"
                        : "+f"(acc[mf][nf][0]), "+f"(acc[mf][nf][1]),
                          "+f"(acc[mf][nf][2]), "+f"(acc[mf][nf][3])
                        : "r"(Af[mf][0]), "r"(Af[mf][1]),
                          "r"(Af[mf][2]), "r"(Af[mf][3]),
                          "r"(Bf[nf][0]), "r"(Bf[nf][1]));
        }
    }

    asm volatile("cp.async.wait_group 0;\n");
    __syncthreads();

    // kh>0 groups publish partials into SMEM (reuse stage memory)
    float* red = sm;                              // [3][128][72]
    if (kh > 0) {
        float* rg = red + (kh - 1) * (128 * BSx);
        #pragma unroll
        for (int mf = 0; mf < 2; ++mf) {
            int rl = wm * 32 + mf * 16 + (lane >> 2);
            #pragma unroll
            for (int nf = 0; nf < 4; ++nf) {
                int col = wn * 32 + nf * 8 + (lane & 3) * 2;
                *(float2*)&rg[rl * BSx + col] =
                    make_float2(acc[mf][nf][0], acc[mf][nf][1]);
                *(float2*)&rg[(rl + 8) * BSx + col] =
                    make_float2(acc[mf][nf][2], acc[mf][nf][3]);
            }
        }
    }
    __syncthreads();

    // kh==0 merges 4 partials + fused epilogue (bias + root + relu)
    if (kh == 0) {
        const float* rg0 = red;
        const float* rg1 = red + 128 * BSx;
        const float* rg2 = red + 256 * BSx;
        #pragma unroll
        for (int mf = 0; mf < 2; ++mf) {
            int rl = wm * 32 + mf * 16 + (lane >> 2);
            int i0 = m0 + rl;
            #pragma unroll
            for (int nf = 0; nf < 4; ++nf) {
                int col = wn * 32 + nf * 8 + (lane & 3) * 2;
                float bv0 = bias[col], bv1 = bias[col + 1];
                float s0 = acc[mf][nf][0], s1 = acc[mf][nf][1];
                float s2 = acc[mf][nf][2], s3 = acc[mf][nf][3];
                float2 p;
                p = *(const float2*)&rg0[rl * BSx + col];        s0 += p.x; s1 += p.y;
                p = *(const float2*)&rg0[(rl + 8) * BSx + col];  s2 += p.x; s3 += p.y;
                p = *(const float2*)&rg1[rl * BSx + col];        s0 += p.x; s1 += p.y;
                p = *(const float2*)&rg1[(rl + 8) * BSx + col];  s2 += p.x; s3 += p.y;
                p = *(const float2*)&rg2[rl * BSx + col];        s0 += p.x; s1 += p.y;
                p = *(const float2*)&rg2[(rl + 8) * BSx + col];  s2 += p.x; s3 += p.y;
                float2 rv0 = *(const float2*)&Radd[(size_t)i0 * 64 + col];
                float2 rv1 = *(const float2*)&Radd[(size_t)(i0 + 8) * 64 + col];
                float2 o0, o1;
                o0.x = fmaxf(s0 + bv0 + rv0.x, 0.f);
                o0.y = fmaxf(s1 + bv1 + rv0.y, 0.f);
                o1.x = fmaxf(s2 + bv0 + rv1.x, 0.f);
                o1.y = fmaxf(s3 + bv1 + rv1.y, 0.f);
                *(float2*)&out[(size_t)i0 * 64 + col] = o0;
                *(float2*)&out[(size_t)(i0 + 8) * 64 + col] = o1;
            }
        }
    }
}

// =============================================================
// kernel_launch: 6 kernels, default stream, graph-capturable.
// =============================================================
extern "C" void kernel_launch(void* const* d_in, const int* in_sizes, int n_in,
                              void* d_out, int out_size) {
    (void)in_sizes; (void)n_in; (void)out_size;
    const float* X   = (const float*)d_in[0];
    const float* adj = (const float*)d_in[1];
    const float* Wr0 = (const float*)d_in[2];
    const float* b0  = (const float*)d_in[3];
    const float* Wo0 = (const float*)d_in[4];
    const float* Wr1 = (const float*)d_in[5];
    const float* b1  = (const float*)d_in[6];
    const float* Wo1 = (const float*)d_in[7];
    const float* Wr2 = (const float*)d_in[8];
    const float* b2  = (const float*)d_in[9];
    const float* Wo2 = (const float*)d_in[10];
    float* out = (float*)d_out;

    float *t, *r, *hA, *hB;
    cudaGetSymbolAddress((void**)&t,  g_t);
    cudaGetSymbolAddress((void**)&r,  g_r);
    cudaGetSymbolAddress((void**)&hA, g_hA);
    cudaGetSymbolAddress((void**)&hB, g_hB);

    const int SMEM_SMALL0 = (128 * 260 + 128 * 68) * 4;  // 167936 (K=256)
    const int SMEM_SMALL1 = (128 * 68 + 128 * 68) * 4;   // 69632  (K=64)

    cudaFuncSetAttribute(small_gemm, cudaFuncAttributeMaxDynamicSharedMemorySize, SMEM_SMALL0);
    cudaFuncSetAttribute(big_gemm,   cudaFuncAttributeMaxDynamicSharedMemorySize, SMEM_BIG);

    // layer 0 (F_in = 256)
    small_gemm<<<128, 256, SMEM_SMALL0>>>(X,  Wr0, Wo0, t, r, 256);
    big_gemm  <<<128, 1024, SMEM_BIG  >>>(adj, t, r, b0, hA);
    // layer 1 (F_in = 64)
    small_gemm<<<128, 256, SMEM_SMALL1>>>(hA, Wr1, Wo1, t, r, 64);
    big_gemm  <<<128, 1024, SMEM_BIG  >>>(adj, t, r, b1, hB);
    // layer 2 (F_in = 64)
    small_gemm<<<128, 256, SMEM_SMALL1>>>(hB, Wr2, Wo2, t, r, 64);
    big_gemm  <<<128, 1024, SMEM_BIG  >>>(adj, t, r, b2, out);
}